// round 15
// baseline (speedup 1.0000x reference)
#include <cuda_runtime.h>
#include <cuda_fp16.h>
#include <cstdint>

// ---------------------------------------------------------------------------
// Pre-split fp16 (hi,lo) operand pairs in global memory.
// GEMM: mma.sync m16n8k16, CTA 128x128, BK=64, cp.async 3-stage (64KB each),
// 512 threads (16 warps of 32x32).
// TERMS=3 (ah*bh + ah*bl + al*bh) on the logit-critical path (G1,G3,G7);
// TERMS=2 (ah*bh + ah*bl) on G2,G4,G5,G6 (analysis: <=1e-4 output impact).
// ---------------------------------------------------------------------------

__device__ __half g_half[314572800];
__device__ float g_float[67108864];

__device__ __forceinline__ uint32_t smem_u32(const void* p) {
    uint32_t a;
    asm("{ .reg .u64 t; cvta.to.shared.u64 t, %1; cvt.u32.u64 %0, t; }" : "=r"(a) : "l"(p));
    return a;
}
__device__ __forceinline__ uint32_t pack_half2(__half lo, __half hi) {
    return (uint32_t)__half_as_ushort(lo) | ((uint32_t)__half_as_ushort(hi) << 16);
}
__device__ __forceinline__ void cp16(uint32_t dst, const void* src) {
    asm volatile("cp.async.cg.shared.global [%0], [%1], 16;" :: "r"(dst), "l"(src));
}
#define CP_COMMIT() asm volatile("cp.async.commit_group;")
#define CP_WAIT1()  asm volatile("cp.async.wait_group 1;")

__device__ __forceinline__ void ldmx4(uint32_t* r, uint32_t addr) {
    asm volatile("ldmatrix.sync.aligned.m8n8.x4.shared.b16 {%0,%1,%2,%3}, [%4];"
                 : "=r"(r[0]), "=r"(r[1]), "=r"(r[2]), "=r"(r[3]) : "r"(addr));
}
__device__ __forceinline__ void mma16816(float* d, const uint32_t* a, uint32_t b0, uint32_t b1) {
    asm volatile("mma.sync.aligned.m16n8k16.row.col.f32.f16.f16.f32 "
                 "{%0,%1,%2,%3}, {%4,%5,%6,%7}, {%8,%9}, {%0,%1,%2,%3};"
                 : "+f"(d[0]), "+f"(d[1]), "+f"(d[2]), "+f"(d[3])
                 : "r"(a[0]), "r"(a[1]), "r"(a[2]), "r"(a[3]), "r"(b0), "r"(b1));
}

// ------------------- MMA GEMM: C = A * B^T (+bias) -------------------
// Smem row (256B): [hi 128B | lo 128B]; each 128B half has 8 16B chunks,
// chunk j stored at j ^ (row & 7).
template<int TERMS, bool BIAS, bool HOUT>
__global__ __launch_bounds__(512, 1)
void mma_gemm(const __half* __restrict__ Ah, const __half* __restrict__ Al,
              const __half* __restrict__ Bh, const __half* __restrict__ Bl,
              float* __restrict__ Cf, __half* __restrict__ Ch, __half* __restrict__ Cl,
              int K, int lda, int ldb, int ldc,
              long long sA, long long sB, long long sC,
              const float* __restrict__ bias)
{
    extern __shared__ char smem[];   // 3 stages x 64KB
    const uint32_t sbase = smem_u32(smem);
    const int tid = threadIdx.x;
    const int w = tid >> 5, lane = tid & 31;
    const int wm = w & 3, wn = w >> 2;     // 4x4 warp grid of 32x32 tiles

    Ah += blockIdx.z * sA; Al += blockIdx.z * sA;
    Bh += blockIdx.z * sB; Bl += blockIdx.z * sB;
    const int rowBase = blockIdx.y << 7;
    const int colBase = blockIdx.x << 7;

    float acc[2][4][4];
#pragma unroll
    for (int i = 0; i < 2; i++)
#pragma unroll
        for (int j = 0; j < 4; j++)
#pragma unroll
            for (int q = 0; q < 4; q++) acc[i][j][q] = 0.f;

    // one 64KB stage: 4096 x 16B chunks, 8 per thread
    auto load_stage = [&](int kt, int s) {
        const uint32_t sb = sbase + s * 65536;
        const int ko = kt << 6;   // halves
#pragma unroll
        for (int i = 0; i < 8; i++) {
            int f = tid + (i << 9);          // 0..4095
            int isB = f >> 11;               // 0:A 1:B
            int ca = f & 2047;
            int r = ca >> 4, c = ca & 15;    // r 0..127, c 0..15
            int ld = isB ? ldb : lda;
            const __half* base = isB ? (Bh + (long long)(colBase + r) * ld)
                                     : (Ah + (long long)(rowBase + r) * ld);
            const __half* basel = isB ? (Bl + (long long)(colBase + r) * ld)
                                      : (Al + (long long)(rowBase + r) * ld);
            const __half* src = (c < 8) ? base + ko + (c << 3)
                                        : basel + ko + ((c - 8) << 3);
            uint32_t dst = sb + (isB ? 32768u : 0u) + (uint32_t)(r << 8)
                         + ((c < 8) ? 0u : 128u)
                         + ((((uint32_t)c & 7u) ^ (uint32_t)(r & 7)) << 4);
            cp16(dst, src);
        }
        CP_COMMIT();
    };

    // ldmatrix lane geometry
    const uint32_t t4 = lane >> 3, trow = lane & 7;
    const uint32_t kpartA = t4 >> 1, rloA = ((t4 & 1) << 3) + trow;
    const uint32_t kpartB = t4 & 1, rloB = ((t4 >> 1) << 3) + trow;

    auto compute = [&](int s) {
        const uint32_t sb = sbase + s * 65536;
#pragma unroll
        for (int kc = 0; kc < 4; kc++) {
            uint32_t Afh[2][4], Afl[2][4], Bfh[2][4], Bfl[2][4];
#pragma unroll
            for (int mc = 0; mc < 2; mc++) {
                uint32_t r = (uint32_t)(wm * 32 + mc * 16) + rloA;
                uint32_t rx = r & 7;
                uint32_t jh = ((uint32_t)(kc * 2) + kpartA) ^ rx;
                ldmx4(Afh[mc], sb + (r << 8) + (jh << 4));
                if (TERMS == 3) {
                    ldmx4(Afl[mc], sb + (r << 8) + 128u + (jh << 4));
                }
            }
#pragma unroll
            for (int nc = 0; nc < 2; nc++) {
                uint32_t r = (uint32_t)(wn * 32 + nc * 16) + rloB;
                uint32_t rx = r & 7;
                uint32_t jh = ((uint32_t)(kc * 2) + kpartB) ^ rx;
                ldmx4(Bfh[nc], sb + 32768u + (r << 8) + (jh << 4));
                ldmx4(Bfl[nc], sb + 32768u + (r << 8) + 128u + (jh << 4));
            }
#pragma unroll
            for (int mc = 0; mc < 2; mc++)
#pragma unroll
                for (int nc = 0; nc < 2; nc++)
#pragma unroll
                    for (int sub = 0; sub < 2; sub++) {
                        float* d = acc[mc][nc * 2 + sub];
                        mma16816(d, Afh[mc], Bfh[nc][sub * 2], Bfh[nc][sub * 2 + 1]);
                        mma16816(d, Afh[mc], Bfl[nc][sub * 2], Bfl[nc][sub * 2 + 1]);
                        if (TERMS == 3)
                            mma16816(d, Afl[mc], Bfh[nc][sub * 2], Bfh[nc][sub * 2 + 1]);
                    }
        }
    };

    const int NT = K >> 6;
    load_stage(0, 0);
    if (NT > 1) load_stage(1, 1); else CP_COMMIT();

    int s = 0, sp = 2;
    for (int kt = 0; kt < NT; kt++) {
        CP_WAIT1();
        __syncthreads();
        if (kt + 2 < NT) load_stage(kt + 2, sp); else CP_COMMIT();
        compute(s);
        s = (s == 2) ? 0 : s + 1;
        sp = (sp == 2) ? 0 : sp + 1;
    }

    // epilogue
#pragma unroll
    for (int mc = 0; mc < 2; mc++) {
        const int r0 = rowBase + wm * 32 + mc * 16 + (lane >> 2);
#pragma unroll
        for (int nsub = 0; nsub < 4; nsub++) {
            const int col = colBase + wn * 32 + nsub * 8 + ((lane & 3) << 1);
            float* d = acc[mc][nsub];
            float bx = 0.f, by = 0.f;
            if (BIAS) { bx = bias[col]; by = bias[col + 1]; }
            float v0x = d[0] + bx, v0y = d[1] + by;
            float v1x = d[2] + bx, v1y = d[3] + by;
            if (HOUT) {
                __half h0x = __float2half_rn(v0x), h0y = __float2half_rn(v0y);
                __half h1x = __float2half_rn(v1x), h1y = __float2half_rn(v1y);
                __half l0x = __float2half_rn(v0x - __half2float(h0x));
                __half l0y = __float2half_rn(v0y - __half2float(h0y));
                __half l1x = __float2half_rn(v1x - __half2float(h1x));
                __half l1y = __float2half_rn(v1y - __half2float(h1y));
                long long o0 = blockIdx.z * sC + (long long)r0 * ldc + col;
                long long o1 = o0 + (long long)8 * ldc;
                *(uint32_t*)(Ch + o0) = pack_half2(h0x, h0y);
                *(uint32_t*)(Cl + o0) = pack_half2(l0x, l0y);
                *(uint32_t*)(Ch + o1) = pack_half2(h1x, h1y);
                *(uint32_t*)(Cl + o1) = pack_half2(l1x, l1y);
            } else {
                long long o0 = blockIdx.z * sC + (long long)r0 * ldc + col;
                *(float2*)(Cf + o0) = make_float2(v0x, v0y);
                *(float2*)(Cf + o0 + (long long)8 * ldc) = make_float2(v1x, v1y);
            }
        }
    }
}

// ------------------------- elementwise / prep -------------------------
__device__ __forceinline__ float block_reduce_sum(float v, float* red) {
    const int tid = threadIdx.x;
#pragma unroll
    for (int o = 16; o; o >>= 1) v += __shfl_xor_sync(0xffffffffu, v, o);
    if ((tid & 31) == 0) red[tid >> 5] = v;
    __syncthreads();
    if (tid < 32) {
        float t = (tid < 8) ? red[tid] : 0.f;
#pragma unroll
        for (int o = 4; o; o >>= 1) t += __shfl_xor_sync(0xffffffffu, t, o);
        if (tid == 0) red[0] = t;
    }
    __syncthreads();
    return red[0];
}
__device__ __forceinline__ float block_reduce_max(float v, float* red) {
    const int tid = threadIdx.x;
#pragma unroll
    for (int o = 16; o; o >>= 1) v = fmaxf(v, __shfl_xor_sync(0xffffffffu, v, o));
    if ((tid & 31) == 0) red[tid >> 5] = v;
    __syncthreads();
    if (tid < 32) {
        float t = (tid < 8) ? red[tid] : -3.4e38f;
#pragma unroll
        for (int o = 4; o; o >>= 1) t = fmaxf(t, __shfl_xor_sync(0xffffffffu, t, o));
        if (tid == 0) red[0] = t;
    }
    __syncthreads();
    return red[0];
}

__device__ __forceinline__ void split4_store(__half* h, __half* l, long long off, float4 v) {
    __half hx = __float2half_rn(v.x), hy = __float2half_rn(v.y);
    __half hz = __float2half_rn(v.z), hw = __float2half_rn(v.w);
    uint2 hv, lv;
    hv.x = pack_half2(hx, hy); hv.y = pack_half2(hz, hw);
    lv.x = pack_half2(__float2half_rn(v.x - __half2float(hx)), __float2half_rn(v.y - __half2float(hy)));
    lv.y = pack_half2(__float2half_rn(v.z - __half2float(hz)), __float2half_rn(v.w - __half2float(hw)));
    *(uint2*)(h + off) = hv;
    *(uint2*)(l + off) = lv;
}

__global__ __launch_bounds__(256)
void convert_pair(const float* __restrict__ src, __half* __restrict__ h, __half* __restrict__ l)
{
    long long i = (long long)blockIdx.x * 256 + threadIdx.x;
    float4 v = ((const float4*)src)[i];
    split4_store(h, l, i << 2, v);
}

__global__ __launch_bounds__(256)
void prep_cat(const float* __restrict__ x, __half* __restrict__ ch, __half* __restrict__ cl)
{
    long long i = (long long)blockIdx.x * 256 + threadIdx.x;
    long long row = i >> 8;
    int c = (int)(i & 255) << 2;
    float4 v = *(const float4*)(x + (row << 10) + c);
    split4_store(ch, cl, (row << 11) + c, v);
}

__global__ __launch_bounds__(256)
void transpose_conv(const float* __restrict__ x, __half* __restrict__ th, __half* __restrict__ tl)
{
    __shared__ float t[32][33];
    const int b = blockIdx.z;
    const int s0 = blockIdx.x << 5, d0 = blockIdx.y << 5;
    const int tx = threadIdx.x & 31, ty0 = threadIdx.x >> 5;
    const long long base = (long long)b << 20;
#pragma unroll
    for (int i = 0; i < 4; i++) {
        int ty = ty0 + i * 8;
        t[ty][tx] = x[base + (long long)(s0 + ty) * 1024 + d0 + tx];
    }
    __syncthreads();
#pragma unroll
    for (int i = 0; i < 4; i++) {
        int ty = ty0 + i * 8;
        float v = t[tx][ty];
        __half h = __float2half_rn(v);
        long long o = base + (long long)(d0 + ty) * 1024 + s0 + tx;
        th[o] = h;
        tl[o] = __float2half_rn(v - __half2float(h));
    }
}

__global__ __launch_bounds__(256)
void normalize_rows(const float* __restrict__ ctx32, __half* __restrict__ ch, __half* __restrict__ cl)
{
    __shared__ float red[8];
    const int half_ = blockIdx.x, row = blockIdx.y, b = blockIdx.z;
    const long long off = ((long long)(b * 1024 + row)) * 2048 + half_ * 1024;
    const int tid = threadIdx.x;
    float4 v = ((const float4*)(ctx32 + off))[tid];
    float s = v.x * v.x + v.y * v.y + v.z * v.z + v.w * v.w;
    s = block_reduce_sum(s, red);
    const float inv = 1.f / fmaxf(sqrtf(s), 1e-12f);
    v.x *= inv; v.y *= inv; v.z *= inv; v.w *= inv;
    split4_store(ch, cl, off + (tid << 2), v);
}

__global__ __launch_bounds__(256)
void softmax_mask(const float* __restrict__ self32, const float* __restrict__ ctxat32,
                  const int* __restrict__ mask,
                  __half* __restrict__ ah, __half* __restrict__ al,
                  const float* __restrict__ Wf, const float* __restrict__ bf)
{
    __shared__ float red[8];
    const int row = blockIdx.x, b = blockIdx.y;
    const long long off = ((long long)(b * 1024 + row)) * 1024;
    const float w0 = Wf[0], w1 = Wf[1], b0 = bf[0];
    const int tid = threadIdx.x;

    float4 sv = ((const float4*)(self32 + off))[tid];
    float4 cv = ((const float4*)(ctxat32 + off))[tid];
    int4 mv = ((const int4*)(mask + off))[tid];

    float l[4];
    l[0] = fmaf(sv.x, w0, fmaf(cv.x, w1, b0));
    l[1] = fmaf(sv.y, w0, fmaf(cv.y, w1, b0));
    l[2] = fmaf(sv.z, w0, fmaf(cv.z, w1, b0));
    l[3] = fmaf(sv.w, w0, fmaf(cv.w, w1, b0));

    float mx = fmaxf(fmaxf(l[0], l[1]), fmaxf(l[2], l[3]));
    mx = block_reduce_max(mx, red);

    float e[4], Z = 0.f, Zm = 0.f;
    const int mk[4] = { mv.x != 0, mv.y != 0, mv.z != 0, mv.w != 0 };
#pragma unroll
    for (int i = 0; i < 4; i++) {
        e[i] = __expf(l[i] - mx);
        Z += e[i];
        Zm += mk[i] ? e[i] : 0.f;
    }
    Z = block_reduce_sum(Z, red);
    __syncthreads();
    Zm = block_reduce_sum(Zm, red);

    const float inv = 1.f / fmaxf(Zm, 1e-12f * Z);
    float4 o;
    o.x = mk[0] ? e[0] * inv : 0.f;
    o.y = mk[1] ? e[1] * inv : 0.f;
    o.z = mk[2] ? e[2] * inv : 0.f;
    o.w = mk[3] ? e[3] * inv : 0.f;
    split4_store(ah, al, off + (tid << 2), o);
}

// ------------------------- launch -------------------------
extern "C" void kernel_launch(void* const* d_in, const int* in_sizes, int n_in,
                              void* d_out, int out_size)
{
    const float* x    = (const float*)d_in[0];
    const int*   mask = (const int*)d_in[1];
    const float* Wqkv = (const float*)d_in[2];
    const float* bqkv = (const float*)d_in[3];
    const float* Wctx = (const float*)d_in[4];
    const float* bctx = (const float*)d_in[5];
    const float* Wf   = (const float*)d_in[6];
    const float* bf   = (const float*)d_in[7];
    const float* Wo   = (const float*)d_in[8];
    const float* bo   = (const float*)d_in[9];
    float* out = (float*)d_out;

    __half* hp; float* fp;
    cudaGetSymbolAddress((void**)&hp, g_half);
    cudaGetSymbolAddress((void**)&fp, g_float);

    __half* cath  = hp;             __half* catl  = hp + 33554432;
    __half* xTh   = hp + 67108864;  __half* xTl   = hp + 83886080;
    __half* qkvh  = hp + 100663296; __half* qkvl  = hp + 134217728;
    __half* adjh  = hp + 167772160; __half* adjl  = hp + 184549376;
    __half* ctxh  = hp + 201326592; __half* ctxl  = hp + 234881024;
    __half* attnh = hp + 268435456; __half* attnl = hp + 285212672;
    __half* wqkvh = hp + 301989888; __half* wqkvl = hp + 304087040;
    __half* wctxh = hp + 306184192; __half* wctxl = hp + 308281344;
    __half* woh   = hp + 310378496; __half* wol   = hp + 312475648;

    float* ctx32   = fp;
    float* self32  = fp + 33554432;
    float* ctxat32 = fp + 50331648;

    const int SMEM = 196608;   // 3 x 64KB
    cudaFuncSetAttribute(mma_gemm<3, true, true>,   cudaFuncAttributeMaxDynamicSharedMemorySize, SMEM);
    cudaFuncSetAttribute(mma_gemm<3, true, false>,  cudaFuncAttributeMaxDynamicSharedMemorySize, SMEM);
    cudaFuncSetAttribute(mma_gemm<3, false, false>, cudaFuncAttributeMaxDynamicSharedMemorySize, SMEM);
    cudaFuncSetAttribute(mma_gemm<2, true, false>,  cudaFuncAttributeMaxDynamicSharedMemorySize, SMEM);
    cudaFuncSetAttribute(mma_gemm<2, false, false>, cudaFuncAttributeMaxDynamicSharedMemorySize, SMEM);
    cudaFuncSetAttribute(mma_gemm<2, false, true>,  cudaFuncAttributeMaxDynamicSharedMemorySize, SMEM);

    const dim3 blk(256), gblk(512);

    // prep: conversions
    prep_cat<<<16384, blk>>>(x, cath, catl);
    transpose_conv<<<dim3(32, 32, 16), blk>>>(x, xTh, xTl);
    convert_pair<<<2048, blk>>>(Wqkv, wqkvh, wqkvl);
    convert_pair<<<2048, blk>>>(Wctx, wctxh, wctxl);
    convert_pair<<<2048, blk>>>(Wo, woh, wol);

    // G1: qkv = x @ Wqkv^T + bqkv  -> half pair   (3-term)
    mma_gemm<3, true, true><<<dim3(16, 128, 1), gblk, SMEM>>>(
        cath, catl, wqkvh, wqkvl, nullptr, qkvh, qkvl,
        1024, 2048, 1024, 2048, 0, 0, 0, bqkv);

    // G2: adj_b = x_b @ x_b^T -> half pair   (2-term)
    mma_gemm<2, false, true><<<dim3(8, 8, 16), gblk, SMEM>>>(
        cath, catl, cath, catl, nullptr, adjh, adjl,
        1024, 2048, 2048, 1024, 2097152, 2097152, 1048576, nullptr);

    // G3: self_b = q_b @ k_b^T -> fp32   (3-term)
    mma_gemm<3, false, false><<<dim3(8, 8, 16), gblk, SMEM>>>(
        qkvh, qkvl, qkvh + 1024, qkvl + 1024, self32, nullptr, nullptr,
        1024, 2048, 2048, 1024, 2097152, 2097152, 1048576, nullptr);

    // G4: ctx_b = adj_b @ Wctx^T + bctx -> fp32   (2-term)
    mma_gemm<2, true, false><<<dim3(16, 8, 16), gblk, SMEM>>>(
        adjh, adjl, wctxh, wctxl, ctx32, nullptr, nullptr,
        1024, 1024, 1024, 2048, 1048576, 0, 2097152, bctx);

    normalize_rows<<<dim3(2, 1024, 16), blk>>>(ctx32, ctxh, ctxl);

    // G5: ctx_attn_b = ctxq_b @ ctxk_b^T -> fp32   (2-term)
    mma_gemm<2, false, false><<<dim3(8, 8, 16), gblk, SMEM>>>(
        ctxh, ctxl, ctxh + 1024, ctxl + 1024, ctxat32, nullptr, nullptr,
        1024, 2048, 2048, 1024, 2097152, 2097152, 1048576, nullptr);

    softmax_mask<<<dim3(1024, 16), blk>>>(self32, ctxat32, mask, attnh, attnl, Wf, bf);

    // G6: vals_b = attn_b @ (xT_b)^T -> half pair into cat[:,1024:]   (2-term)
    mma_gemm<2, false, true><<<dim3(8, 8, 16), gblk, SMEM>>>(
        attnh, attnl, xTh, xTl, nullptr, cath + 1024, catl + 1024,
        1024, 1024, 1024, 2048, 1048576, 1048576, 2097152, nullptr);

    // G7: out = cat @ Wo^T + bo  (K=2048) -> fp32   (3-term)
    mma_gemm<3, true, false><<<dim3(8, 128, 1), gblk, SMEM>>>(
        cath, catl, woh, wol, out, nullptr, nullptr,
        2048, 2048, 2048, 1024, 0, 0, 0, bo);
}

// round 16
// speedup vs baseline: 1.0031x; 1.0031x over previous
#include <cuda_runtime.h>
#include <cuda_fp16.h>
#include <cstdint>

// ---------------------------------------------------------------------------
// Pre-split fp16 (hi,lo) operand pairs in global memory.
// GEMM: mma.sync m16n8k16, CTA 128x128, BK=64, cp.async 3-stage (64KB each),
// 512 threads (16 warps of 32x32).
// TERMS=3 (ah*bh + ah*bl + al*bh) on the logit-critical path (G1,G3,G7);
// TERMS=2 (ah*bh + ah*bl) on G2,G4,G5,G6 (analysis: <=1e-4 output impact).
// ---------------------------------------------------------------------------

__device__ __half g_half[314572800];
__device__ float g_float[67108864];

__device__ __forceinline__ uint32_t smem_u32(const void* p) {
    uint32_t a;
    asm("{ .reg .u64 t; cvta.to.shared.u64 t, %1; cvt.u32.u64 %0, t; }" : "=r"(a) : "l"(p));
    return a;
}
__device__ __forceinline__ uint32_t pack_half2(__half lo, __half hi) {
    return (uint32_t)__half_as_ushort(lo) | ((uint32_t)__half_as_ushort(hi) << 16);
}
__device__ __forceinline__ void cp16(uint32_t dst, const void* src) {
    asm volatile("cp.async.cg.shared.global [%0], [%1], 16;" :: "r"(dst), "l"(src));
}
#define CP_COMMIT() asm volatile("cp.async.commit_group;")
#define CP_WAIT1()  asm volatile("cp.async.wait_group 1;")

__device__ __forceinline__ void ldmx4(uint32_t* r, uint32_t addr) {
    asm volatile("ldmatrix.sync.aligned.m8n8.x4.shared.b16 {%0,%1,%2,%3}, [%4];"
                 : "=r"(r[0]), "=r"(r[1]), "=r"(r[2]), "=r"(r[3]) : "r"(addr));
}
__device__ __forceinline__ void mma16816(float* d, const uint32_t* a, uint32_t b0, uint32_t b1) {
    asm volatile("mma.sync.aligned.m16n8k16.row.col.f32.f16.f16.f32 "
                 "{%0,%1,%2,%3}, {%4,%5,%6,%7}, {%8,%9}, {%0,%1,%2,%3};"
                 : "+f"(d[0]), "+f"(d[1]), "+f"(d[2]), "+f"(d[3])
                 : "r"(a[0]), "r"(a[1]), "r"(a[2]), "r"(a[3]), "r"(b0), "r"(b1));
}

// ------------------- MMA GEMM: C = A * B^T (+bias) -------------------
// Smem row (256B): [hi 128B | lo 128B]; each 128B half has 8 16B chunks,
// chunk j stored at j ^ (row & 7).
template<int TERMS, bool BIAS, bool HOUT>
__global__ __launch_bounds__(512, 1)
void mma_gemm(const __half* __restrict__ Ah, const __half* __restrict__ Al,
              const __half* __restrict__ Bh, const __half* __restrict__ Bl,
              float* __restrict__ Cf, __half* __restrict__ Ch, __half* __restrict__ Cl,
              int K, int lda, int ldb, int ldc,
              long long sA, long long sB, long long sC,
              const float* __restrict__ bias)
{
    extern __shared__ char smem[];   // 3 stages x 64KB
    const uint32_t sbase = smem_u32(smem);
    const int tid = threadIdx.x;
    const int w = tid >> 5, lane = tid & 31;
    const int wm = w & 3, wn = w >> 2;     // 4x4 warp grid of 32x32 tiles

    Ah += blockIdx.z * sA; Al += blockIdx.z * sA;
    Bh += blockIdx.z * sB; Bl += blockIdx.z * sB;
    const int rowBase = blockIdx.y << 7;
    const int colBase = blockIdx.x << 7;

    float acc[2][4][4];
#pragma unroll
    for (int i = 0; i < 2; i++)
#pragma unroll
        for (int j = 0; j < 4; j++)
#pragma unroll
            for (int q = 0; q < 4; q++) acc[i][j][q] = 0.f;

    // one 64KB stage: 4096 x 16B chunks, 8 per thread
    auto load_stage = [&](int kt, int s) {
        const uint32_t sb = sbase + s * 65536;
        const int ko = kt << 6;   // halves
#pragma unroll
        for (int i = 0; i < 8; i++) {
            int f = tid + (i << 9);          // 0..4095
            int isB = f >> 11;               // 0:A 1:B
            int ca = f & 2047;
            int r = ca >> 4, c = ca & 15;    // r 0..127, c 0..15
            int ld = isB ? ldb : lda;
            const __half* base = isB ? (Bh + (long long)(colBase + r) * ld)
                                     : (Ah + (long long)(rowBase + r) * ld);
            const __half* basel = isB ? (Bl + (long long)(colBase + r) * ld)
                                      : (Al + (long long)(rowBase + r) * ld);
            const __half* src = (c < 8) ? base + ko + (c << 3)
                                        : basel + ko + ((c - 8) << 3);
            uint32_t dst = sb + (isB ? 32768u : 0u) + (uint32_t)(r << 8)
                         + ((c < 8) ? 0u : 128u)
                         + ((((uint32_t)c & 7u) ^ (uint32_t)(r & 7)) << 4);
            cp16(dst, src);
        }
        CP_COMMIT();
    };

    // ldmatrix lane geometry
    const uint32_t t4 = lane >> 3, trow = lane & 7;
    const uint32_t kpartA = t4 >> 1, rloA = ((t4 & 1) << 3) + trow;
    const uint32_t kpartB = t4 & 1, rloB = ((t4 >> 1) << 3) + trow;

    auto compute = [&](int s) {
        const uint32_t sb = sbase + s * 65536;
#pragma unroll
        for (int kc = 0; kc < 4; kc++) {
            uint32_t Afh[2][4], Afl[2][4], Bfh[2][4], Bfl[2][4];
#pragma unroll
            for (int mc = 0; mc < 2; mc++) {
                uint32_t r = (uint32_t)(wm * 32 + mc * 16) + rloA;
                uint32_t rx = r & 7;
                uint32_t jh = ((uint32_t)(kc * 2) + kpartA) ^ rx;
                ldmx4(Afh[mc], sb + (r << 8) + (jh << 4));
                if (TERMS == 3) {
                    ldmx4(Afl[mc], sb + (r << 8) + 128u + (jh << 4));
                }
            }
#pragma unroll
            for (int nc = 0; nc < 2; nc++) {
                uint32_t r = (uint32_t)(wn * 32 + nc * 16) + rloB;
                uint32_t rx = r & 7;
                uint32_t jh = ((uint32_t)(kc * 2) + kpartB) ^ rx;
                ldmx4(Bfh[nc], sb + 32768u + (r << 8) + (jh << 4));
                ldmx4(Bfl[nc], sb + 32768u + (r << 8) + 128u + (jh << 4));
            }
#pragma unroll
            for (int mc = 0; mc < 2; mc++)
#pragma unroll
                for (int nc = 0; nc < 2; nc++)
#pragma unroll
                    for (int sub = 0; sub < 2; sub++) {
                        float* d = acc[mc][nc * 2 + sub];
                        mma16816(d, Afh[mc], Bfh[nc][sub * 2], Bfh[nc][sub * 2 + 1]);
                        mma16816(d, Afh[mc], Bfl[nc][sub * 2], Bfl[nc][sub * 2 + 1]);
                        if (TERMS == 3)
                            mma16816(d, Afl[mc], Bfh[nc][sub * 2], Bfh[nc][sub * 2 + 1]);
                    }
        }
    };

    const int NT = K >> 6;
    load_stage(0, 0);
    if (NT > 1) load_stage(1, 1); else CP_COMMIT();

    int s = 0, sp = 2;
    for (int kt = 0; kt < NT; kt++) {
        CP_WAIT1();
        __syncthreads();
        if (kt + 2 < NT) load_stage(kt + 2, sp); else CP_COMMIT();
        compute(s);
        s = (s == 2) ? 0 : s + 1;
        sp = (sp == 2) ? 0 : sp + 1;
    }

    // epilogue
#pragma unroll
    for (int mc = 0; mc < 2; mc++) {
        const int r0 = rowBase + wm * 32 + mc * 16 + (lane >> 2);
#pragma unroll
        for (int nsub = 0; nsub < 4; nsub++) {
            const int col = colBase + wn * 32 + nsub * 8 + ((lane & 3) << 1);
            float* d = acc[mc][nsub];
            float bx = 0.f, by = 0.f;
            if (BIAS) { bx = bias[col]; by = bias[col + 1]; }
            float v0x = d[0] + bx, v0y = d[1] + by;
            float v1x = d[2] + bx, v1y = d[3] + by;
            if (HOUT) {
                __half h0x = __float2half_rn(v0x), h0y = __float2half_rn(v0y);
                __half h1x = __float2half_rn(v1x), h1y = __float2half_rn(v1y);
                __half l0x = __float2half_rn(v0x - __half2float(h0x));
                __half l0y = __float2half_rn(v0y - __half2float(h0y));
                __half l1x = __float2half_rn(v1x - __half2float(h1x));
                __half l1y = __float2half_rn(v1y - __half2float(h1y));
                long long o0 = blockIdx.z * sC + (long long)r0 * ldc + col;
                long long o1 = o0 + (long long)8 * ldc;
                *(uint32_t*)(Ch + o0) = pack_half2(h0x, h0y);
                *(uint32_t*)(Cl + o0) = pack_half2(l0x, l0y);
                *(uint32_t*)(Ch + o1) = pack_half2(h1x, h1y);
                *(uint32_t*)(Cl + o1) = pack_half2(l1x, l1y);
            } else {
                long long o0 = blockIdx.z * sC + (long long)r0 * ldc + col;
                *(float2*)(Cf + o0) = make_float2(v0x, v0y);
                *(float2*)(Cf + o0 + (long long)8 * ldc) = make_float2(v1x, v1y);
            }
        }
    }
}

// ------------------------- elementwise / prep -------------------------
__device__ __forceinline__ float block_reduce_sum(float v, float* red) {
    const int tid = threadIdx.x;
#pragma unroll
    for (int o = 16; o; o >>= 1) v += __shfl_xor_sync(0xffffffffu, v, o);
    if ((tid & 31) == 0) red[tid >> 5] = v;
    __syncthreads();
    if (tid < 32) {
        float t = (tid < 8) ? red[tid] : 0.f;
#pragma unroll
        for (int o = 4; o; o >>= 1) t += __shfl_xor_sync(0xffffffffu, t, o);
        if (tid == 0) red[0] = t;
    }
    __syncthreads();
    return red[0];
}
__device__ __forceinline__ float block_reduce_max(float v, float* red) {
    const int tid = threadIdx.x;
#pragma unroll
    for (int o = 16; o; o >>= 1) v = fmaxf(v, __shfl_xor_sync(0xffffffffu, v, o));
    if ((tid & 31) == 0) red[tid >> 5] = v;
    __syncthreads();
    if (tid < 32) {
        float t = (tid < 8) ? red[tid] : -3.4e38f;
#pragma unroll
        for (int o = 4; o; o >>= 1) t = fmaxf(t, __shfl_xor_sync(0xffffffffu, t, o));
        if (tid == 0) red[0] = t;
    }
    __syncthreads();
    return red[0];
}

__device__ __forceinline__ void split4_store(__half* h, __half* l, long long off, float4 v) {
    __half hx = __float2half_rn(v.x), hy = __float2half_rn(v.y);
    __half hz = __float2half_rn(v.z), hw = __float2half_rn(v.w);
    uint2 hv, lv;
    hv.x = pack_half2(hx, hy); hv.y = pack_half2(hz, hw);
    lv.x = pack_half2(__float2half_rn(v.x - __half2float(hx)), __float2half_rn(v.y - __half2float(hy)));
    lv.y = pack_half2(__float2half_rn(v.z - __half2float(hz)), __float2half_rn(v.w - __half2float(hw)));
    *(uint2*)(h + off) = hv;
    *(uint2*)(l + off) = lv;
}

__global__ __launch_bounds__(256)
void convert_pair(const float* __restrict__ src, __half* __restrict__ h, __half* __restrict__ l)
{
    long long i = (long long)blockIdx.x * 256 + threadIdx.x;
    float4 v = ((const float4*)src)[i];
    split4_store(h, l, i << 2, v);
}

__global__ __launch_bounds__(256)
void prep_cat(const float* __restrict__ x, __half* __restrict__ ch, __half* __restrict__ cl)
{
    long long i = (long long)blockIdx.x * 256 + threadIdx.x;
    long long row = i >> 8;
    int c = (int)(i & 255) << 2;
    float4 v = *(const float4*)(x + (row << 10) + c);
    split4_store(ch, cl, (row << 11) + c, v);
}

__global__ __launch_bounds__(256)
void transpose_conv(const float* __restrict__ x, __half* __restrict__ th, __half* __restrict__ tl)
{
    __shared__ float t[32][33];
    const int b = blockIdx.z;
    const int s0 = blockIdx.x << 5, d0 = blockIdx.y << 5;
    const int tx = threadIdx.x & 31, ty0 = threadIdx.x >> 5;
    const long long base = (long long)b << 20;
#pragma unroll
    for (int i = 0; i < 4; i++) {
        int ty = ty0 + i * 8;
        t[ty][tx] = x[base + (long long)(s0 + ty) * 1024 + d0 + tx];
    }
    __syncthreads();
#pragma unroll
    for (int i = 0; i < 4; i++) {
        int ty = ty0 + i * 8;
        float v = t[tx][ty];
        __half h = __float2half_rn(v);
        long long o = base + (long long)(d0 + ty) * 1024 + s0 + tx;
        th[o] = h;
        tl[o] = __float2half_rn(v - __half2float(h));
    }
}

__global__ __launch_bounds__(256)
void normalize_rows(const float* __restrict__ ctx32, __half* __restrict__ ch, __half* __restrict__ cl)
{
    __shared__ float red[8];
    const int half_ = blockIdx.x, row = blockIdx.y, b = blockIdx.z;
    const long long off = ((long long)(b * 1024 + row)) * 2048 + half_ * 1024;
    const int tid = threadIdx.x;
    float4 v = ((const float4*)(ctx32 + off))[tid];
    float s = v.x * v.x + v.y * v.y + v.z * v.z + v.w * v.w;
    s = block_reduce_sum(s, red);
    const float inv = 1.f / fmaxf(sqrtf(s), 1e-12f);
    v.x *= inv; v.y *= inv; v.z *= inv; v.w *= inv;
    split4_store(ch, cl, off + (tid << 2), v);
}

__global__ __launch_bounds__(256)
void softmax_mask(const float* __restrict__ self32, const float* __restrict__ ctxat32,
                  const int* __restrict__ mask,
                  __half* __restrict__ ah, __half* __restrict__ al,
                  const float* __restrict__ Wf, const float* __restrict__ bf)
{
    __shared__ float red[8];
    const int row = blockIdx.x, b = blockIdx.y;
    const long long off = ((long long)(b * 1024 + row)) * 1024;
    const float w0 = Wf[0], w1 = Wf[1], b0 = bf[0];
    const int tid = threadIdx.x;

    float4 sv = ((const float4*)(self32 + off))[tid];
    float4 cv = ((const float4*)(ctxat32 + off))[tid];
    int4 mv = ((const int4*)(mask + off))[tid];

    float l[4];
    l[0] = fmaf(sv.x, w0, fmaf(cv.x, w1, b0));
    l[1] = fmaf(sv.y, w0, fmaf(cv.y, w1, b0));
    l[2] = fmaf(sv.z, w0, fmaf(cv.z, w1, b0));
    l[3] = fmaf(sv.w, w0, fmaf(cv.w, w1, b0));

    float mx = fmaxf(fmaxf(l[0], l[1]), fmaxf(l[2], l[3]));
    mx = block_reduce_max(mx, red);

    float e[4], Z = 0.f, Zm = 0.f;
    const int mk[4] = { mv.x != 0, mv.y != 0, mv.z != 0, mv.w != 0 };
#pragma unroll
    for (int i = 0; i < 4; i++) {
        e[i] = __expf(l[i] - mx);
        Z += e[i];
        Zm += mk[i] ? e[i] : 0.f;
    }
    Z = block_reduce_sum(Z, red);
    __syncthreads();
    Zm = block_reduce_sum(Zm, red);

    const float inv = 1.f / fmaxf(Zm, 1e-12f * Z);
    float4 o;
    o.x = mk[0] ? e[0] * inv : 0.f;
    o.y = mk[1] ? e[1] * inv : 0.f;
    o.z = mk[2] ? e[2] * inv : 0.f;
    o.w = mk[3] ? e[3] * inv : 0.f;
    split4_store(ah, al, off + (tid << 2), o);
}

// ------------------------- launch -------------------------
extern "C" void kernel_launch(void* const* d_in, const int* in_sizes, int n_in,
                              void* d_out, int out_size)
{
    const float* x    = (const float*)d_in[0];
    const int*   mask = (const int*)d_in[1];
    const float* Wqkv = (const float*)d_in[2];
    const float* bqkv = (const float*)d_in[3];
    const float* Wctx = (const float*)d_in[4];
    const float* bctx = (const float*)d_in[5];
    const float* Wf   = (const float*)d_in[6];
    const float* bf   = (const float*)d_in[7];
    const float* Wo   = (const float*)d_in[8];
    const float* bo   = (const float*)d_in[9];
    float* out = (float*)d_out;

    __half* hp; float* fp;
    cudaGetSymbolAddress((void**)&hp, g_half);
    cudaGetSymbolAddress((void**)&fp, g_float);

    __half* cath  = hp;             __half* catl  = hp + 33554432;
    __half* xTh   = hp + 67108864;  __half* xTl   = hp + 83886080;
    __half* qkvh  = hp + 100663296; __half* qkvl  = hp + 134217728;
    __half* adjh  = hp + 167772160; __half* adjl  = hp + 184549376;
    __half* ctxh  = hp + 201326592; __half* ctxl  = hp + 234881024;
    __half* attnh = hp + 268435456; __half* attnl = hp + 285212672;
    __half* wqkvh = hp + 301989888; __half* wqkvl = hp + 304087040;
    __half* wctxh = hp + 306184192; __half* wctxl = hp + 308281344;
    __half* woh   = hp + 310378496; __half* wol   = hp + 312475648;

    float* ctx32   = fp;
    float* self32  = fp + 33554432;
    float* ctxat32 = fp + 50331648;

    const int SMEM = 196608;   // 3 x 64KB
    cudaFuncSetAttribute(mma_gemm<3, true, true>,   cudaFuncAttributeMaxDynamicSharedMemorySize, SMEM);
    cudaFuncSetAttribute(mma_gemm<3, true, false>,  cudaFuncAttributeMaxDynamicSharedMemorySize, SMEM);
    cudaFuncSetAttribute(mma_gemm<3, false, false>, cudaFuncAttributeMaxDynamicSharedMemorySize, SMEM);
    cudaFuncSetAttribute(mma_gemm<2, true, false>,  cudaFuncAttributeMaxDynamicSharedMemorySize, SMEM);
    cudaFuncSetAttribute(mma_gemm<2, false, false>, cudaFuncAttributeMaxDynamicSharedMemorySize, SMEM);
    cudaFuncSetAttribute(mma_gemm<2, false, true>,  cudaFuncAttributeMaxDynamicSharedMemorySize, SMEM);

    const dim3 blk(256), gblk(512);

    // prep: conversions
    prep_cat<<<16384, blk>>>(x, cath, catl);
    transpose_conv<<<dim3(32, 32, 16), blk>>>(x, xTh, xTl);
    convert_pair<<<2048, blk>>>(Wqkv, wqkvh, wqkvl);
    convert_pair<<<2048, blk>>>(Wctx, wctxh, wctxl);
    convert_pair<<<2048, blk>>>(Wo, woh, wol);

    // G1: qkv = x @ Wqkv^T + bqkv  -> half pair   (3-term)
    mma_gemm<3, true, true><<<dim3(16, 128, 1), gblk, SMEM>>>(
        cath, catl, wqkvh, wqkvl, nullptr, qkvh, qkvl,
        1024, 2048, 1024, 2048, 0, 0, 0, bqkv);

    // G2: adj_b = x_b @ x_b^T -> half pair   (2-term)
    mma_gemm<2, false, true><<<dim3(8, 8, 16), gblk, SMEM>>>(
        cath, catl, cath, catl, nullptr, adjh, adjl,
        1024, 2048, 2048, 1024, 2097152, 2097152, 1048576, nullptr);

    // G3: self_b = q_b @ k_b^T -> fp32   (3-term)
    mma_gemm<3, false, false><<<dim3(8, 8, 16), gblk, SMEM>>>(
        qkvh, qkvl, qkvh + 1024, qkvl + 1024, self32, nullptr, nullptr,
        1024, 2048, 2048, 1024, 2097152, 2097152, 1048576, nullptr);

    // G4: ctx_b = adj_b @ Wctx^T + bctx -> fp32   (2-term)
    mma_gemm<2, true, false><<<dim3(16, 8, 16), gblk, SMEM>>>(
        adjh, adjl, wctxh, wctxl, ctx32, nullptr, nullptr,
        1024, 1024, 1024, 2048, 1048576, 0, 2097152, bctx);

    normalize_rows<<<dim3(2, 1024, 16), blk>>>(ctx32, ctxh, ctxl);

    // G5: ctx_attn_b = ctxq_b @ ctxk_b^T -> fp32   (2-term)
    mma_gemm<2, false, false><<<dim3(8, 8, 16), gblk, SMEM>>>(
        ctxh, ctxl, ctxh + 1024, ctxl + 1024, ctxat32, nullptr, nullptr,
        1024, 2048, 2048, 1024, 2097152, 2097152, 1048576, nullptr);

    softmax_mask<<<dim3(1024, 16), blk>>>(self32, ctxat32, mask, attnh, attnl, Wf, bf);

    // G6: vals_b = attn_b @ (xT_b)^T -> half pair into cat[:,1024:]   (2-term)
    mma_gemm<2, false, true><<<dim3(8, 8, 16), gblk, SMEM>>>(
        attnh, attnl, xTh, xTl, nullptr, cath + 1024, catl + 1024,
        1024, 1024, 1024, 2048, 1048576, 1048576, 2097152, nullptr);

    // G7: out = cat @ Wo^T + bo  (K=2048) -> fp32   (3-term)
    mma_gemm<3, true, false><<<dim3(8, 128, 1), gblk, SMEM>>>(
        cath, catl, woh, wol, out, nullptr, nullptr,
        2048, 2048, 2048, 1024, 0, 0, 0, bo);
}